// round 4
// baseline (speedup 1.0000x reference)
#include <cuda_runtime.h>

#define R  5
#define KW 11
#define BW 32
#define TILE_H 8
#define PY 2
#define TLW (BW + 2*R)        // 42
#define TLH (TILE_H + 2*R)    // 18
#define H 256
#define W 256
#define CHW (H*W)

// c_i = -0.5 * (1/sigma_i) * log2(e), folded so weight = ex2(sum c_i * d_i^2)
#define CA (-0.07213475204444817f)   // sigma 10.0  (ch 0,1)
#define CB (-36.06737602222409f)     // sigma 0.02  (ch 2,3,4)
#define CC (-7.213475204444817f)     // sigma 0.1   (ch 5,6,7)

__device__ __forceinline__ float ex2f(float x) {
    float y;
    asm("ex2.approx.ftz.f32 %0, %1;" : "=f"(y) : "f"(x));
    return y;
}

__device__ __forceinline__ int refl(int i, int n) {
    if (i < 0)  i = -i;
    if (i >= n) i = 2*n - 2 - i;
    return i;
}

__device__ __forceinline__ float maha8(const float4 g0, const float4 g1,
                                       const float4 c0, const float4 c1) {
    float d, m;
    d = g0.x - c0.x;  m = (CA * d) * d;
    d = g0.y - c0.y;  m = fmaf(CA * d, d, m);
    d = g0.z - c0.z;  m = fmaf(CB * d, d, m);
    d = g0.w - c0.w;  m = fmaf(CB * d, d, m);
    d = g1.x - c1.x;  m = fmaf(CB * d, d, m);
    d = g1.y - c1.y;  m = fmaf(CC * d, d, m);
    d = g1.z - c1.z;  m = fmaf(CC * d, d, m);
    d = g1.w - c1.w;  m = fmaf(CC * d, d, m);
    return m;
}

__global__ __launch_bounds__(256, 4)
void jbf_kernel(const float* __restrict__ img,
                const float* __restrict__ gd,
                float* __restrict__ out)
{
    __shared__ float4 sg0[TLH][TLW];
    __shared__ float4 sg1[TLH][TLW];
    __shared__ float4 si [TLH][TLW];
    __shared__ float4 redA[4][BW];
    __shared__ float4 redB[4][BW];

    const int b   = blockIdx.z;
    const int tx0 = blockIdx.x * BW;
    const int ty0 = blockIdx.y * TILE_H;

    const float* gb = gd  + (size_t)b * 8 * CHW;
    const float* ib = img + (size_t)b * 3 * CHW;

    const int tid = threadIdx.y * BW + threadIdx.x;

    // Cooperative halo load with reflect padding (256 threads)
    for (int i = tid; i < TLH * TLW; i += 256) {
        int ly = i / TLW;
        int lxx = i - ly * TLW;
        int gy = refl(ty0 + ly - R, H);
        int gx = refl(tx0 + lxx - R, W);
        int off = gy * W + gx;
        sg0[ly][lxx] = make_float4(gb[off],         gb[CHW   + off],
                                   gb[2*CHW + off], gb[3*CHW + off]);
        sg1[ly][lxx] = make_float4(gb[4*CHW + off], gb[5*CHW + off],
                                   gb[6*CHW + off], gb[7*CHW + off]);
        si [ly][lxx] = make_float4(ib[off], ib[CHW + off], ib[2*CHW + off], 0.0f);
    }
    __syncthreads();

    const int lx   = threadIdx.x;
    const int ty   = threadIdx.y;     // 0..7
    const int half = ty >> 2;         // 0: e in 0..5,  1: e in 6..11
    const int g    = ty & 3;          // pixel-pair group 0..3
    const int lyb  = g * PY;          // tile row of pixel A; B = lyb+1

    const float4 c0a = sg0[lyb + R][lx + R];
    const float4 c1a = sg1[lyb + R][lx + R];

    // Incremental Mahalanobis constants (cB loaded transiently, not kept live)
    float e0, e1, e2, e3, e4, e5, e6, e7, Kc;
    {
        const float4 c0b = sg0[lyb + R + 1][lx + R];
        const float4 c1b = sg1[lyb + R + 1][lx + R];
        const float q0 = c0a.x - c0b.x, q1 = c0a.y - c0b.y;
        const float q2 = c0a.z - c0b.z, q3 = c0a.w - c0b.w;
        const float q4 = c1a.x - c1b.x, q5 = c1a.y - c1b.y;
        const float q6 = c1a.z - c1b.z, q7 = c1a.w - c1b.w;
        e0 = 2.0f*CA*q0; e1 = 2.0f*CA*q1;
        e2 = 2.0f*CB*q2; e3 = 2.0f*CB*q3; e4 = 2.0f*CB*q4;
        e5 = 2.0f*CC*q5; e6 = 2.0f*CC*q6; e7 = 2.0f*CC*q7;
        Kc =      (CA*q0)*q0;
        Kc = fmaf( CA*q1, q1, Kc);
        Kc = fmaf( CB*q2, q2, Kc);
        Kc = fmaf( CB*q3, q3, Kc);
        Kc = fmaf( CB*q4, q4, Kc);
        Kc = fmaf( CC*q5, q5, Kc);
        Kc = fmaf( CC*q6, q6, Kc);
        Kc = fmaf( CC*q7, q7, Kc);
    }

    float wsA = 0.0f, axA = 0.0f, ayA = 0.0f, azA = 0.0f;
    float wsB = 0.0f, axB = 0.0f, ayB = 0.0f, azB = 0.0f;

    // Dual rows: 5 per half (half0: e=1..5, half1: e=6..10)
    const int ebase = half ? 6 : 1;
    #pragma unroll 1
    for (int k = 0; k < 5; ++k) {
        const int e = ebase + k;
        const float4* r0 = &sg0[lyb + e][lx];
        const float4* r1 = &sg1[lyb + e][lx];
        const float4* rp = &si [lyb + e][lx];
        #pragma unroll
        for (int dx = 0; dx < KW; ++dx) {
            float4 g0 = r0[dx], g1 = r1[dx], p = rp[dx];

            float d0 = g0.x - c0a.x, d1 = g0.y - c0a.y;
            float d2 = g0.z - c0a.z, d3 = g0.w - c0a.w;
            float d4 = g1.x - c1a.x, d5 = g1.y - c1a.y;
            float d6 = g1.z - c1a.z, d7 = g1.w - c1a.w;

            float mA;
            mA =      (CA*d0)*d0;
            mA = fmaf( CA*d1, d1, mA);
            mA = fmaf( CB*d2, d2, mA);
            mA = fmaf( CB*d3, d3, mA);
            mA = fmaf( CB*d4, d4, mA);
            mA = fmaf( CC*d5, d5, mA);
            mA = fmaf( CC*d6, d6, mA);
            mA = fmaf( CC*d7, d7, mA);

            float t;
            t = fmaf(e0, d0, Kc);
            t = fmaf(e1, d1, t);
            t = fmaf(e2, d2, t);
            t = fmaf(e3, d3, t);
            t = fmaf(e4, d4, t);
            t = fmaf(e5, d5, t);
            t = fmaf(e6, d6, t);
            t = fmaf(e7, d7, t);
            float mB = mA + t;

            float wA = ex2f(mA);
            float wB = ex2f(mB);

            axA = fmaf(wA, p.x, axA);
            ayA = fmaf(wA, p.y, ayA);
            azA = fmaf(wA, p.z, azA);
            wsA += wA;
            axB = fmaf(wB, p.x, axB);
            ayB = fmaf(wB, p.y, ayB);
            azB = fmaf(wB, p.z, azB);
            wsB += wB;
        }
    }

    // Single rows: half0 does e=0 (pixel A only), half1 does e=11 (pixel B only)
    if (half == 0) {
        const float4* r0 = &sg0[lyb][lx];
        const float4* r1 = &sg1[lyb][lx];
        const float4* rp = &si [lyb][lx];
        #pragma unroll
        for (int dx = 0; dx < KW; ++dx) {
            float4 g0 = r0[dx], g1 = r1[dx], p = rp[dx];
            float w = ex2f(maha8(g0, g1, c0a, c1a));
            axA = fmaf(w, p.x, axA);
            ayA = fmaf(w, p.y, ayA);
            azA = fmaf(w, p.z, azA);
            wsA += w;
        }
    } else {
        // reload B centers from smem (kept out of the loop's live set)
        const float4 c0b = sg0[lyb + R + 1][lx + R];
        const float4 c1b = sg1[lyb + R + 1][lx + R];
        const float4* r0 = &sg0[lyb + 11][lx];
        const float4* r1 = &sg1[lyb + 11][lx];
        const float4* rp = &si [lyb + 11][lx];
        #pragma unroll
        for (int dx = 0; dx < KW; ++dx) {
            float4 g0 = r0[dx], g1 = r1[dx], p = rp[dx];
            float w = ex2f(maha8(g0, g1, c0b, c1b));
            axB = fmaf(w, p.x, axB);
            ayB = fmaf(w, p.y, ayB);
            azB = fmaf(w, p.z, azB);
            wsB += w;
        }
    }

    __syncthreads();
    if (half == 1) {
        redA[g][lx] = make_float4(axA, ayA, azA, wsA);
        redB[g][lx] = make_float4(axB, ayB, azB, wsB);
    }
    __syncthreads();

    if (half == 0) {
        float4 rA = redA[g][lx];
        float4 rB = redB[g][lx];
        axA += rA.x; ayA += rA.y; azA += rA.z; wsA += rA.w;
        axB += rB.x; ayB += rB.y; azB += rB.z; wsB += rB.w;

        const int oy0 = ty0 + lyb;
        const int ox  = tx0 + lx;
        float* ob = out + (size_t)b * 3 * CHW + oy0 * W + ox;

        const float invA = 1.0f / wsA;
        ob[0]     = axA * invA;
        ob[CHW]   = ayA * invA;
        ob[2*CHW] = azA * invA;

        const float invB = 1.0f / wsB;
        ob[W]         = axB * invB;
        ob[CHW + W]   = ayB * invB;
        ob[2*CHW + W] = azB * invB;
    }
}

extern "C" void kernel_launch(void* const* d_in, const int* in_sizes, int n_in,
                              void* d_out, int out_size)
{
    const float* img = (const float*)d_in[0];   // (2,3,256,256)
    const float* gd  = (const float*)d_in[1];   // (2,8,256,256)
    float* out = (float*)d_out;                 // (2,3,256,256)

    dim3 block(BW, 8);
    dim3 grid(W / BW, H / TILE_H, 2);
    jbf_kernel<<<grid, block>>>(img, gd, out);
}

// round 5
// speedup vs baseline: 1.0980x; 1.0980x over previous
#include <cuda_runtime.h>

#define R  5
#define KW 11
#define BW 32
#define TILE_H 8
#define PY 2
#define TLW (BW + 2*R)        // 42
#define TLH (TILE_H + 2*R)    // 18
#define H 256
#define W 256
#define CHW (H*W)

// c_i = -0.5 * (1/sigma_i) * log2(e), folded so weight = ex2(sum c_i * d_i^2)
#define CA (-0.07213475204444817f)   // sigma 10.0  (ch 0,1)
#define CB (-36.06737602222409f)     // sigma 0.02  (ch 2,3,4)
#define CC (-7.213475204444817f)     // sigma 0.1   (ch 5,6,7)

typedef unsigned long long ull;

__device__ __forceinline__ float ex2f(float x) {
    float y;
    asm("ex2.approx.ftz.f32 %0, %1;" : "=f"(y) : "f"(x));
    return y;
}
__device__ __forceinline__ ull pk2(float lo, float hi) {
    ull r; asm("mov.b64 %0, {%1, %2};" : "=l"(r) : "f"(lo), "f"(hi)); return r;
}
__device__ __forceinline__ void upk(ull v, float& lo, float& hi) {
    asm("mov.b64 {%0, %1}, %2;" : "=f"(lo), "=f"(hi) : "l"(v));
}
__device__ __forceinline__ ull addx2(ull a, ull b) {
    ull r; asm("add.rn.f32x2 %0, %1, %2;" : "=l"(r) : "l"(a), "l"(b)); return r;
}
__device__ __forceinline__ ull mulx2(ull a, ull b) {
    ull r; asm("mul.rn.f32x2 %0, %1, %2;" : "=l"(r) : "l"(a), "l"(b)); return r;
}
__device__ __forceinline__ ull fmax2(ull a, ull b, ull c) {
    ull r; asm("fma.rn.f32x2 %0, %1, %2, %3;" : "=l"(r) : "l"(a), "l"(b), "l"(c)); return r;
}
__device__ __forceinline__ ull d2u(double d) { return __double_as_longlong(d); }

__device__ __forceinline__ int refl(int i, int n) {
    if (i < 0)  i = -i;
    if (i >= n) i = 2*n - 2 - i;
    return i;
}

// packed Mahalanobis: returns scalar m for one center (nc = negated packed center)
__device__ __forceinline__ float maha_pk(ull g01, ull g23, ull g45, ull g67,
                                         ull nc01, ull nc23, ull nc45, ull nc67,
                                         ull K01, ull K23, ull K45, ull K67,
                                         ull& d01, ull& d23, ull& d45, ull& d67)
{
    d01 = addx2(g01, nc01);
    d23 = addx2(g23, nc23);
    d45 = addx2(g45, nc45);
    d67 = addx2(g67, nc67);
    ull s01 = mulx2(d01, d01);
    ull s23 = mulx2(d23, d23);
    ull s45 = mulx2(d45, d45);
    ull s67 = mulx2(d67, d67);
    ull acc = mulx2(s01, K01);
    acc = fmax2(s23, K23, acc);
    acc = fmax2(s45, K45, acc);
    acc = fmax2(s67, K67, acc);
    float lo, hi; upk(acc, lo, hi);
    return lo + hi;
}

__global__ __launch_bounds__(256, 3)
void jbf_kernel(const float* __restrict__ img,
                const float* __restrict__ gd,
                float* __restrict__ out)
{
    __shared__ float4 sg0[TLH][TLW];
    __shared__ float4 sg1[TLH][TLW];
    __shared__ float4 si [TLH][TLW];
    __shared__ float4 redA[4][BW];
    __shared__ float4 redB[4][BW];

    const int b   = blockIdx.z;
    const int tx0 = blockIdx.x * BW;
    const int ty0 = blockIdx.y * TILE_H;

    const float* gb = gd  + (size_t)b * 8 * CHW;
    const float* ib = img + (size_t)b * 3 * CHW;

    const int tid = threadIdx.y * BW + threadIdx.x;

    // Cooperative halo load with reflect padding (si.w = 1.0 -> free wsum)
    for (int i = tid; i < TLH * TLW; i += 256) {
        int ly = i / TLW;
        int lxx = i - ly * TLW;
        int gy = refl(ty0 + ly - R, H);
        int gx = refl(tx0 + lxx - R, W);
        int off = gy * W + gx;
        sg0[ly][lxx] = make_float4(gb[off],         gb[CHW   + off],
                                   gb[2*CHW + off], gb[3*CHW + off]);
        sg1[ly][lxx] = make_float4(gb[4*CHW + off], gb[5*CHW + off],
                                   gb[6*CHW + off], gb[7*CHW + off]);
        si [ly][lxx] = make_float4(ib[off], ib[CHW + off], ib[2*CHW + off], 1.0f);
    }
    __syncthreads();

    const int lx   = threadIdx.x;
    const int ty   = threadIdx.y;     // 0..7
    const int half = ty >> 2;         // 0: e in 0..5,  1: e in 6..11
    const int g    = ty & 3;          // pixel-pair group 0..3
    const int lyb  = g * PY;          // tile row of pixel A; B = lyb+1

    // Packed sigma coefficients (channel pairs 01,23,45,67)
    const ull K01 = pk2(CA, CA);
    const ull K23 = pk2(CB, CB);
    const ull K45 = pk2(CB, CC);
    const ull K67 = pk2(CC, CC);

    // Centers A (negated, packed)
    const float4 c0a = sg0[lyb + R][lx + R];
    const float4 c1a = sg1[lyb + R][lx + R];
    const ull ncA01 = pk2(-c0a.x, -c0a.y);
    const ull ncA23 = pk2(-c0a.z, -c0a.w);
    const ull ncA45 = pk2(-c1a.x, -c1a.y);
    const ull ncA67 = pk2(-c1a.z, -c1a.w);

    // Incremental constants for pixel B: mB = mA + sum(e_i*d_i) + Kc
    ull E01, E23, E45, E67, KcPk;
    {
        const float4 c0b = sg0[lyb + R + 1][lx + R];
        const float4 c1b = sg1[lyb + R + 1][lx + R];
        const float q0 = c0a.x - c0b.x, q1 = c0a.y - c0b.y;
        const float q2 = c0a.z - c0b.z, q3 = c0a.w - c0b.w;
        const float q4 = c1a.x - c1b.x, q5 = c1a.y - c1b.y;
        const float q6 = c1a.z - c1b.z, q7 = c1a.w - c1b.w;
        E01 = pk2(2.0f*CA*q0, 2.0f*CA*q1);
        E23 = pk2(2.0f*CB*q2, 2.0f*CB*q3);
        E45 = pk2(2.0f*CB*q4, 2.0f*CC*q5);
        E67 = pk2(2.0f*CC*q6, 2.0f*CC*q7);
        float Kc;
        Kc =      (CA*q0)*q0;
        Kc = fmaf( CA*q1, q1, Kc);
        Kc = fmaf( CB*q2, q2, Kc);
        Kc = fmaf( CB*q3, q3, Kc);
        Kc = fmaf( CB*q4, q4, Kc);
        Kc = fmaf( CC*q5, q5, Kc);
        Kc = fmaf( CC*q6, q6, Kc);
        Kc = fmaf( CC*q7, q7, Kc);
        KcPk = pk2(Kc, 0.0f);
    }

    // Packed accumulators: (ax,ay) and (az,ws)
    ull aA0 = pk2(0.0f, 0.0f), aA1 = aA0;
    ull aB0 = aA0, aB1 = aA0;

    // Dual rows: 5 per half (half0: e=1..5, half1: e=6..10)
    const int ebase = half ? 6 : 1;
    #pragma unroll 1
    for (int k = 0; k < 5; ++k) {
        const int e = ebase + k;
        const double2* r0 = (const double2*)&sg0[lyb + e][lx];
        const double2* r1 = (const double2*)&sg1[lyb + e][lx];
        const double2* rp = (const double2*)&si [lyb + e][lx];
        #pragma unroll
        for (int dx = 0; dx < KW; ++dx) {
            double2 G0 = r0[dx], G1 = r1[dx], P = rp[dx];
            ull g01 = d2u(G0.x), g23 = d2u(G0.y);
            ull g45 = d2u(G1.x), g67 = d2u(G1.y);
            ull p01 = d2u(P.x),  p23 = d2u(P.y);

            ull d01, d23, d45, d67;
            float mA = maha_pk(g01, g23, g45, g67,
                               ncA01, ncA23, ncA45, ncA67,
                               K01, K23, K45, K67,
                               d01, d23, d45, d67);

            ull tacc = fmax2(d01, E01, KcPk);
            tacc = fmax2(d23, E23, tacc);
            tacc = fmax2(d45, E45, tacc);
            tacc = fmax2(d67, E67, tacc);
            float tlo, thi; upk(tacc, tlo, thi);
            float mB = mA + (tlo + thi);

            float wA = ex2f(mA);
            float wB = ex2f(mB);
            ull wApk = pk2(wA, wA);
            ull wBpk = pk2(wB, wB);

            aA0 = fmax2(wApk, p01, aA0);
            aA1 = fmax2(wApk, p23, aA1);
            aB0 = fmax2(wBpk, p01, aB0);
            aB1 = fmax2(wBpk, p23, aB1);
        }
    }

    // Single rows: half0 does e=0 (pixel A), half1 does e=11 (pixel B)
    {
        const int e = half ? 11 : 0;
        ull nc01 = ncA01, nc23 = ncA23, nc45 = ncA45, nc67 = ncA67;
        if (half) {
            const float4 c0b = sg0[lyb + R + 1][lx + R];
            const float4 c1b = sg1[lyb + R + 1][lx + R];
            nc01 = pk2(-c0b.x, -c0b.y);
            nc23 = pk2(-c0b.z, -c0b.w);
            nc45 = pk2(-c1b.x, -c1b.y);
            nc67 = pk2(-c1b.z, -c1b.w);
        }
        const double2* r0 = (const double2*)&sg0[lyb + e][lx];
        const double2* r1 = (const double2*)&sg1[lyb + e][lx];
        const double2* rp = (const double2*)&si [lyb + e][lx];
        ull a0 = pk2(0.0f, 0.0f), a1 = a0;
        #pragma unroll
        for (int dx = 0; dx < KW; ++dx) {
            double2 G0 = r0[dx], G1 = r1[dx], P = rp[dx];
            ull d01, d23, d45, d67;
            float m = maha_pk(d2u(G0.x), d2u(G0.y), d2u(G1.x), d2u(G1.y),
                              nc01, nc23, nc45, nc67,
                              K01, K23, K45, K67,
                              d01, d23, d45, d67);
            float w = ex2f(m);
            ull wpk = pk2(w, w);
            a0 = fmax2(wpk, d2u(P.x), a0);
            a1 = fmax2(wpk, d2u(P.y), a1);
        }
        if (half) { aB0 = addx2(aB0, a0); aB1 = addx2(aB1, a1); }
        else      { aA0 = addx2(aA0, a0); aA1 = addx2(aA1, a1); }
    }

    // Unpack accumulators
    float axA, ayA, azA, wsA, axB, ayB, azB, wsB;
    upk(aA0, axA, ayA); upk(aA1, azA, wsA);
    upk(aB0, axB, ayB); upk(aB1, azB, wsB);

    __syncthreads();
    if (half == 1) {
        redA[g][lx] = make_float4(axA, ayA, azA, wsA);
        redB[g][lx] = make_float4(axB, ayB, azB, wsB);
    }
    __syncthreads();

    if (half == 0) {
        float4 rA = redA[g][lx];
        float4 rB = redB[g][lx];
        axA += rA.x; ayA += rA.y; azA += rA.z; wsA += rA.w;
        axB += rB.x; ayB += rB.y; azB += rB.z; wsB += rB.w;

        const int oy0 = ty0 + lyb;
        const int ox  = tx0 + lx;
        float* ob = out + (size_t)b * 3 * CHW + oy0 * W + ox;

        const float invA = 1.0f / wsA;
        ob[0]     = axA * invA;
        ob[CHW]   = ayA * invA;
        ob[2*CHW] = azA * invA;

        const float invB = 1.0f / wsB;
        ob[W]         = axB * invB;
        ob[CHW + W]   = ayB * invB;
        ob[2*CHW + W] = azB * invB;
    }
}

extern "C" void kernel_launch(void* const* d_in, const int* in_sizes, int n_in,
                              void* d_out, int out_size)
{
    const float* img = (const float*)d_in[0];   // (2,3,256,256)
    const float* gd  = (const float*)d_in[1];   // (2,8,256,256)
    float* out = (float*)d_out;                 // (2,3,256,256)

    dim3 block(BW, 8);
    dim3 grid(W / BW, H / TILE_H, 2);
    jbf_kernel<<<grid, block>>>(img, gd, out);
}